// round 1
// baseline (speedup 1.0000x reference)
#include <cuda_runtime.h>
#include <cstdint>
#include <cstddef>

// ---------------- problem constants ----------------
#define B_   2
#define L_   2048
#define DM   2048          // d_model
#define DI   4096          // d_inner
#define EI   8192          // 2*d_inner
#define DS   16            // d_state
#define DTR  128           // dt_rank
#define XD   160           // dt_rank + 2*d_state
#define ML   (B_*L_)       // 4096 rows

// ---------------- scratch (device globals; no allocation allowed) ----------------
__device__ float g_xz  [(size_t)ML * EI];   // in_proj output [b*l, 8192]
__device__ float g_xc  [(size_t)ML * DI];   // conv+silu x    [b*l, 4096]
__device__ float g_xdbl[(size_t)ML * XD];   // x_proj output  [b*l, 160]
__device__ float g_dt  [(size_t)ML * DI];   // softplus(dt)   [b*l, 4096]
__device__ float g_y   [(size_t)ML * DI];   // scan output    [b*l, 4096]

// ---------------- generic tiled SGEMM: C[M,N] = A[M,K] * B[N,K]^T ----------------
// A row-major with leading dim lda, B row-major (weights) ldb=K stride, C ldc.
// EPI: 0 = none, 1 = softplus(v + bias[n])
template<int BM, int BN, int BK, int TM, int TN, int EPI>
__global__ __launch_bounds__(256)
void sgemm_kernel(int M, int N, int K,
                  const float* __restrict__ A, int lda,
                  const float* __restrict__ Bw, int ldb,
                  float* __restrict__ C, int ldc,
                  const float* __restrict__ bias)
{
    __shared__ float As[BK][BM];
    __shared__ float Bs[BK][BN];

    const int tid = threadIdx.x;
    const int tx  = tid & 15;     // n direction (16)
    const int ty  = tid >> 4;     // m direction (16)
    const int bm  = blockIdx.y * BM;
    const int bn  = blockIdx.x * BN;

    float acc[TM][TN];
    #pragma unroll
    for (int i = 0; i < TM; i++)
        #pragma unroll
        for (int j = 0; j < TN; j++) acc[i][j] = 0.0f;

    // float4 tile loaders
    const int a_m = tid / (BK/4);
    const int a_k = (tid % (BK/4)) * 4;
    const int b_n = tid / (BK/4);
    const int b_k = (tid % (BK/4)) * 4;

    for (int k0 = 0; k0 < K; k0 += BK) {
        if (tid < (BM*BK/4)) {
            float4 v = *(const float4*)&A[(size_t)(bm + a_m)*lda + k0 + a_k];
            As[a_k+0][a_m] = v.x; As[a_k+1][a_m] = v.y;
            As[a_k+2][a_m] = v.z; As[a_k+3][a_m] = v.w;
        }
        if (tid < (BN*BK/4)) {
            float4 v = *(const float4*)&Bw[(size_t)(bn + b_n)*ldb + k0 + b_k];
            Bs[b_k+0][b_n] = v.x; Bs[b_k+1][b_n] = v.y;
            Bs[b_k+2][b_n] = v.z; Bs[b_k+3][b_n] = v.w;
        }
        __syncthreads();

        #pragma unroll
        for (int k = 0; k < BK; k++) {
            float rm[TM], rn[TN];
            #pragma unroll
            for (int i = 0; i < TM; i++) rm[i] = As[k][ty*TM + i];
            #pragma unroll
            for (int j = 0; j < TN; j++) rn[j] = Bs[k][tx*TN + j];
            #pragma unroll
            for (int i = 0; i < TM; i++)
                #pragma unroll
                for (int j = 0; j < TN; j++)
                    acc[i][j] += rm[i] * rn[j];
        }
        __syncthreads();
    }

    #pragma unroll
    for (int i = 0; i < TM; i++) {
        const int m = bm + ty*TM + i;
        #pragma unroll
        for (int j = 0; j < TN; j++) {
            const int n = bn + tx*TN + j;
            float v = acc[i][j];
            if (EPI == 1) {
                v += bias[n];
                v = (v > 20.0f) ? v : log1pf(__expf(v));   // softplus
            }
            C[(size_t)m*ldc + n] = v;
        }
    }
}

// ---------------- depthwise causal conv(k=4) + bias + silu ----------------
// x half of g_xz (cols [0,DI)) -> g_xc, layout [b*l, DI]; rolling window over l.
__global__ __launch_bounds__(256)
void conv_silu_kernel(const float* __restrict__ xz,
                      const float* __restrict__ w,
                      const float* __restrict__ bias,
                      float* __restrict__ xc)
{
    const int d = blockIdx.x * blockDim.x + threadIdx.x;   // channel
    const int b = blockIdx.y;
    const float w0 = w[d*4+0], w1 = w[d*4+1], w2 = w[d*4+2], w3 = w[d*4+3];
    const float bi = bias[d];
    const float* px = xz + (size_t)b * L_ * EI + d;
    float*       po = xc + (size_t)b * L_ * DI + d;

    float x0 = 0.f, x1 = 0.f, x2 = 0.f;
    #pragma unroll 4
    for (int l = 0; l < L_; l++) {
        float x3 = px[(size_t)l * EI];
        float v  = w0*x0 + w1*x1 + w2*x2 + w3*x3 + bi;
        v = v / (1.0f + __expf(-v));                      // silu
        po[(size_t)l * DI] = v;
        x0 = x1; x1 = x2; x2 = x3;
    }
}

// ---------------- selective scan (sequential over L) ----------------
// one thread per (b, d); 128 channels per block; Bm/Cm in double-buffered smem.
__global__ __launch_bounds__(128)
void scan_kernel(const float* __restrict__ xz,    // z at col DI..EI
                 const float* __restrict__ xc,
                 const float* __restrict__ dt,
                 const float* __restrict__ xdbl,  // [ML,160]: B at 128, C at 144
                 const float* __restrict__ A_log,
                 const float* __restrict__ Dp,
                 float* __restrict__ y)
{
    const int b = blockIdx.y;
    const int d = blockIdx.x * blockDim.x + threadIdx.x;
    __shared__ float sBC[2][32];   // [buf][0..15]=B, [16..31]=C

    float negA[DS];
    #pragma unroll
    for (int n = 0; n < DS; n++) negA[n] = -__expf(A_log[d*DS + n]);

    // power-chain validity: negA[n] == (n+1)*negA[0] (true for reference A_log)
    bool chain = (negA[0] != 0.0f);
    #pragma unroll
    for (int n = 1; n < DS; n++) {
        float r = negA[n] - (float)(n+1) * negA[0];
        if (fabsf(r) > 1e-4f * fabsf(negA[n])) chain = false;
    }

    const float Dd = Dp[d];
    float h[DS];
    #pragma unroll
    for (int n = 0; n < DS; n++) h[n] = 0.0f;

    const size_t rb = (size_t)b * L_;
    const float* pdt = dt   + rb * DI + d;
    const float* pxc = xc   + rb * DI + d;
    const float* pz  = xz   + rb * EI + DI + d;
    const float* pbc = xdbl + rb * XD + DTR;
    float*       py  = y    + rb * DI + d;

    // preload l = 0
    if (threadIdx.x < 32) sBC[0][threadIdx.x] = pbc[threadIdx.x];
    float dt_c = pdt[0], x_c = pxc[0], z_c = pz[0];
    __syncthreads();

    float dt_n = 0.f, x_n = 0.f, z_n = 0.f;
    for (int l = 0; l < L_; l++) {
        const int cur = l & 1, nxt = cur ^ 1;
        if (l + 1 < L_) {
            if (threadIdx.x < 32)
                sBC[nxt][threadIdx.x] = pbc[(size_t)(l+1) * XD + threadIdx.x];
            dt_n = pdt[(size_t)(l+1) * DI];
            x_n  = pxc[(size_t)(l+1) * DI];
            z_n  = pz [(size_t)(l+1) * EI];
        }

        const float dtv = dt_c;
        float dA[DS];
        if (chain) {
            float base = __expf(dtv * negA[0]);       // 1 MUFU
            dA[0] = base;
            dA[1] = base * base;
            #pragma unroll
            for (int n = 2; n < DS; n++)              // base^(n+1), log-depth tree
                dA[n] = dA[(n-1) >> 1] * dA[n >> 1];
        } else {
            #pragma unroll
            for (int n = 0; n < DS; n++) dA[n] = __expf(dtv * negA[n]);
        }

        const float du = dtv * x_c;
        float yv = 0.0f;
        #pragma unroll
        for (int n = 0; n < DS; n++) {
            h[n] = h[n] * dA[n] + du * sBC[cur][n];
            yv  += h[n] * sBC[cur][16 + n];
        }
        yv += x_c * Dd;
        const float zs = z_c / (1.0f + __expf(-z_c)); // silu(z)
        py[(size_t)l * DI] = yv * zs;

        dt_c = dt_n; x_c = x_n; z_c = z_n;
        __syncthreads();
    }
}

// ---------------- launch ----------------
extern "C" void kernel_launch(void* const* d_in, const int* in_sizes, int n_in,
                              void* d_out, int out_size)
{
    const float* hs    = (const float*)d_in[0];  // [B,L,DM]
    const float* w_in  = (const float*)d_in[1];  // [EI,DM]
    const float* convw = (const float*)d_in[2];  // [DI,1,4]
    const float* convb = (const float*)d_in[3];  // [DI]
    const float* xpw   = (const float*)d_in[4];  // [XD,DI]
    const float* dtw   = (const float*)d_in[5];  // [DI,DTR]
    const float* dtb   = (const float*)d_in[6];  // [DI]
    const float* outw  = (const float*)d_in[7];  // [DM,DI]
    const float* Alog  = (const float*)d_in[8];  // [DI,DS]
    const float* Dp    = (const float*)d_in[9];  // [DI]
    float*       out   = (float*)d_out;          // [B,L,DM]

    float *xz, *xc, *xdbl, *dtb_, *yb;
    cudaGetSymbolAddress((void**)&xz,   g_xz);
    cudaGetSymbolAddress((void**)&xc,   g_xc);
    cudaGetSymbolAddress((void**)&xdbl, g_xdbl);
    cudaGetSymbolAddress((void**)&dtb_, g_dt);
    cudaGetSymbolAddress((void**)&yb,   g_y);

    const dim3 t256(256);

    // 1) in_proj: xz[ML,EI] = hs[ML,DM] * w_in[EI,DM]^T
    sgemm_kernel<64,64,16,4,4,0><<<dim3(EI/64, ML/64), t256>>>(
        ML, EI, DM, hs, DM, w_in, DM, xz, EI, nullptr);

    // 2) depthwise conv + silu -> xc[ML,DI]
    conv_silu_kernel<<<dim3(DI/256, B_), t256>>>(xz, convw, convb, xc);

    // 3) x_proj: xdbl[ML,XD] = xc * xpw^T   (N=160 -> BN=32)
    sgemm_kernel<64,32,16,4,2,0><<<dim3(XD/32, ML/64), t256>>>(
        ML, XD, DI, xc, DI, xpw, DI, xdbl, XD, nullptr);

    // 4) dt_proj + softplus: dt[ML,DI] = softplus(xdbl[:, :128] * dtw^T + dtb)
    sgemm_kernel<64,64,16,4,4,1><<<dim3(DI/64, ML/64), t256>>>(
        ML, DI, DTR, xdbl, XD, dtw, DTR, dtb_, DI, dtb);

    // 5) selective scan -> y[ML,DI]
    scan_kernel<<<dim3(DI/128, B_), dim3(128)>>>(
        xz, xc, dtb_, xdbl, Alog, Dp, yb);

    // 6) out_proj: out[ML,DM] = y * outw^T
    sgemm_kernel<64,64,16,4,4,0><<<dim3(DM/64, ML/64), t256>>>(
        ML, DM, DI, yb, DI, outw, DI, out, DM, nullptr);
}

// round 3
// speedup vs baseline: 1.8839x; 1.8839x over previous
#include <cuda_runtime.h>
#include <cstdint>
#include <cstddef>

// ---------------- problem constants ----------------
#define B_   2
#define L_   2048
#define DM   2048          // d_model
#define DI   4096          // d_inner
#define EI   8192          // 2*d_inner
#define DS   16            // d_state
#define DTR  128           // dt_rank
#define XD   160           // dt_rank + 2*d_state
#define ML   (B_*L_)       // 4096 rows

// ---------------- scratch (device globals; no allocation allowed) ----------------
__device__ float g_xz  [(size_t)ML * EI];   // in_proj output [b*l, 8192]
__device__ float g_xc  [(size_t)ML * DI];   // conv+silu x    [b*l, 4096]
__device__ float g_xdbl[(size_t)ML * XD];   // x_proj output  [b*l, 160]
__device__ float g_dt  [(size_t)ML * DI];   // softplus(dt)   [b*l, 4096]
__device__ float g_y   [(size_t)ML * DI];   // scan output    [b*l, 4096]

// ================= TF32 tensor-core GEMM =================
// C[M,N] = A[M,K] * B[N,K]^T   (A row-major lda, B row-major ldb, C row-major ldc)
// BM=128, BN=128, BK=16, 256 threads, 8 warps as 2(m) x 4(n), warp tile 64x32.
// EPI: 0 = none, 1 = softplus(v + bias[n])

__device__ __forceinline__ unsigned f2tf32(float f) {
    unsigned u;
    asm("cvt.rna.tf32.f32 %0, %1;" : "=r"(u) : "f"(f));
    return u;
}

#define SSTRIDE 18   // smem row stride (floats), pos 0..15 + pad 2

template<int EPI>
__global__ __launch_bounds__(256)
void mma_gemm(int M, int N, int K,
              const float* __restrict__ A, int lda,
              const float* __restrict__ Bw, int ldb,
              float* __restrict__ C, int ldc,
              const float* __restrict__ bias)
{
    __shared__ float As[2][128 * SSTRIDE];
    __shared__ float Bs[2][128 * SSTRIDE];

    const int tid  = threadIdx.x;
    const int lane = tid & 31;
    const int warp = tid >> 5;
    const int wm   = (warp & 1) * 64;   // warp m offset within block
    const int wn   = (warp >> 1) * 32;  // warp n offset within block
    const int bm   = blockIdx.y * 128;
    const int bn   = blockIdx.x * 128;

    // global loader indices: each thread loads 2 float4 of A and 2 of B
    const int lr  = tid >> 2;          // row 0..63  (and +64)
    const int lc  = (tid & 3) * 4;     // k-col base {0,4,8,12}
    // paired-k smem position base for a float4 starting at k=lc:
    // pos(k) = (k/8)*8 + (k%8%4)*2 + (k%8)/4  -> stride 2 within the float4
    const int pbase = ((lc >> 3) << 3) | ((lc >> 2) & 1);

    const float* gA0 = A  + (size_t)(bm + lr)      * lda + lc;
    const float* gA1 = A  + (size_t)(bm + lr + 64) * lda + lc;
    const float* gB0 = Bw + (size_t)(bn + lr)      * ldb + lc;
    const float* gB1 = Bw + (size_t)(bn + lr + 64) * ldb + lc;

    float acc[4][4][4];   // [m-tile][n-tile][c0..c3]
    #pragma unroll
    for (int i = 0; i < 4; i++)
        #pragma unroll
        for (int j = 0; j < 4; j++)
            #pragma unroll
            for (int r = 0; r < 4; r++) acc[i][j][r] = 0.0f;

    // fragment smem bases
    const int a_row = wm + (lane >> 2);
    const int b_row = wn + (lane >> 2);
    const int fcol  = (lane & 3) * 2;

    const int KT = K / 16;

    // ---- prologue: load tile 0 into buffer 0 ----
    {
        float4 a0 = *(const float4*)gA0;
        float4 a1 = *(const float4*)gA1;
        float4 b0 = *(const float4*)gB0;
        float4 b1 = *(const float4*)gB1;
        float* as = As[0] + lr * SSTRIDE;
        float* bs = Bs[0] + lr * SSTRIDE;
        as[pbase+0] = __uint_as_float(f2tf32(a0.x));
        as[pbase+2] = __uint_as_float(f2tf32(a0.y));
        as[pbase+4] = __uint_as_float(f2tf32(a0.z));
        as[pbase+6] = __uint_as_float(f2tf32(a0.w));
        as[64*SSTRIDE + pbase+0] = __uint_as_float(f2tf32(a1.x));
        as[64*SSTRIDE + pbase+2] = __uint_as_float(f2tf32(a1.y));
        as[64*SSTRIDE + pbase+4] = __uint_as_float(f2tf32(a1.z));
        as[64*SSTRIDE + pbase+6] = __uint_as_float(f2tf32(a1.w));
        bs[pbase+0] = __uint_as_float(f2tf32(b0.x));
        bs[pbase+2] = __uint_as_float(f2tf32(b0.y));
        bs[pbase+4] = __uint_as_float(f2tf32(b0.z));
        bs[pbase+6] = __uint_as_float(f2tf32(b0.w));
        bs[64*SSTRIDE + pbase+0] = __uint_as_float(f2tf32(b1.x));
        bs[64*SSTRIDE + pbase+2] = __uint_as_float(f2tf32(b1.y));
        bs[64*SSTRIDE + pbase+4] = __uint_as_float(f2tf32(b1.z));
        bs[64*SSTRIDE + pbase+6] = __uint_as_float(f2tf32(b1.w));
    }
    __syncthreads();

    int cur = 0;
    for (int kt = 0; kt < KT; kt++) {
        float4 a0, a1, b0, b1;
        const bool more = (kt + 1) < KT;
        if (more) {
            const size_t ko = (size_t)(kt + 1) * 16;
            a0 = *(const float4*)(gA0 + ko);
            a1 = *(const float4*)(gA1 + ko);
            b0 = *(const float4*)(gB0 + ko);
            b1 = *(const float4*)(gB1 + ko);
        }

        // ---- compute on buffer cur ----
        const float* asb = As[cur];
        const float* bsb = Bs[cur];
        #pragma unroll
        for (int ks = 0; ks < 2; ks++) {
            const int off = ks * 8 + fcol;
            unsigned af[4][4];   // [m-tile][a0,a1,a2,a3]
            unsigned bf[4][2];
            #pragma unroll
            for (int i = 0; i < 4; i++) {
                float2 lo = *(const float2*)&asb[(a_row + i*16    ) * SSTRIDE + off];
                float2 hi = *(const float2*)&asb[(a_row + i*16 + 8) * SSTRIDE + off];
                af[i][0] = __float_as_uint(lo.x);
                af[i][2] = __float_as_uint(lo.y);
                af[i][1] = __float_as_uint(hi.x);
                af[i][3] = __float_as_uint(hi.y);
            }
            #pragma unroll
            for (int j = 0; j < 4; j++) {
                float2 v = *(const float2*)&bsb[(b_row + j*8) * SSTRIDE + off];
                bf[j][0] = __float_as_uint(v.x);
                bf[j][1] = __float_as_uint(v.y);
            }
            #pragma unroll
            for (int i = 0; i < 4; i++)
                #pragma unroll
                for (int j = 0; j < 4; j++) {
                    asm volatile(
                        "mma.sync.aligned.m16n8k8.row.col.f32.tf32.tf32.f32 "
                        "{%0,%1,%2,%3}, {%4,%5,%6,%7}, {%8,%9}, {%0,%1,%2,%3};"
                        : "+f"(acc[i][j][0]), "+f"(acc[i][j][1]),
                          "+f"(acc[i][j][2]), "+f"(acc[i][j][3])
                        : "r"(af[i][0]), "r"(af[i][1]), "r"(af[i][2]), "r"(af[i][3]),
                          "r"(bf[j][0]), "r"(bf[j][1]));
                }
        }

        if (more) {
            const int nxt = cur ^ 1;
            float* as = As[nxt] + lr * SSTRIDE;
            float* bs = Bs[nxt] + lr * SSTRIDE;
            as[pbase+0] = __uint_as_float(f2tf32(a0.x));
            as[pbase+2] = __uint_as_float(f2tf32(a0.y));
            as[pbase+4] = __uint_as_float(f2tf32(a0.z));
            as[pbase+6] = __uint_as_float(f2tf32(a0.w));
            as[64*SSTRIDE + pbase+0] = __uint_as_float(f2tf32(a1.x));
            as[64*SSTRIDE + pbase+2] = __uint_as_float(f2tf32(a1.y));
            as[64*SSTRIDE + pbase+4] = __uint_as_float(f2tf32(a1.z));
            as[64*SSTRIDE + pbase+6] = __uint_as_float(f2tf32(a1.w));
            bs[pbase+0] = __uint_as_float(f2tf32(b0.x));
            bs[pbase+2] = __uint_as_float(f2tf32(b0.y));
            bs[pbase+4] = __uint_as_float(f2tf32(b0.z));
            bs[pbase+6] = __uint_as_float(f2tf32(b0.w));
            bs[64*SSTRIDE + pbase+0] = __uint_as_float(f2tf32(b1.x));
            bs[64*SSTRIDE + pbase+2] = __uint_as_float(f2tf32(b1.y));
            bs[64*SSTRIDE + pbase+4] = __uint_as_float(f2tf32(b1.z));
            bs[64*SSTRIDE + pbase+6] = __uint_as_float(f2tf32(b1.w));
            __syncthreads();
            cur = nxt;
        }
    }

    // ---- epilogue ----
    #pragma unroll
    for (int i = 0; i < 4; i++) {
        const int r0 = bm + wm + i*16 + (lane >> 2);
        #pragma unroll
        for (int j = 0; j < 4; j++) {
            const int c0 = bn + wn + j*8 + (lane & 3)*2;
            float v0 = acc[i][j][0], v1 = acc[i][j][1];
            float v2 = acc[i][j][2], v3 = acc[i][j][3];
            if (EPI == 1) {
                const float bA = bias[c0], bB = bias[c0+1];
                v0 += bA; v1 += bB; v2 += bA; v3 += bB;
                v0 = (v0 > 20.0f) ? v0 : log1pf(__expf(v0));
                v1 = (v1 > 20.0f) ? v1 : log1pf(__expf(v1));
                v2 = (v2 > 20.0f) ? v2 : log1pf(__expf(v2));
                v3 = (v3 > 20.0f) ? v3 : log1pf(__expf(v3));
            }
            *(float2*)&C[(size_t)r0 * ldc + c0]       = make_float2(v0, v1);
            *(float2*)&C[(size_t)(r0+8) * ldc + c0]   = make_float2(v2, v3);
        }
    }
}

// ---------------- fp32 tiled SGEMM (kept for x_proj: N=160) ----------------
template<int BM, int BN, int BK, int TM, int TN>
__global__ __launch_bounds__(256)
void sgemm_kernel(int M, int N, int K,
                  const float* __restrict__ A, int lda,
                  const float* __restrict__ Bw, int ldb,
                  float* __restrict__ C, int ldc)
{
    __shared__ float As[BK][BM];
    __shared__ float Bs[BK][BN];

    const int tid = threadIdx.x;
    const int tx  = tid & 15;
    const int ty  = tid >> 4;
    const int bm  = blockIdx.y * BM;
    const int bn  = blockIdx.x * BN;

    float acc[TM][TN];
    #pragma unroll
    for (int i = 0; i < TM; i++)
        #pragma unroll
        for (int j = 0; j < TN; j++) acc[i][j] = 0.0f;

    const int a_m = tid / (BK/4);
    const int a_k = (tid % (BK/4)) * 4;
    const int b_n = tid / (BK/4);
    const int b_k = (tid % (BK/4)) * 4;

    for (int k0 = 0; k0 < K; k0 += BK) {
        if (tid < (BM*BK/4)) {
            float4 v = *(const float4*)&A[(size_t)(bm + a_m)*lda + k0 + a_k];
            As[a_k+0][a_m] = v.x; As[a_k+1][a_m] = v.y;
            As[a_k+2][a_m] = v.z; As[a_k+3][a_m] = v.w;
        }
        if (tid < (BN*BK/4)) {
            float4 v = *(const float4*)&Bw[(size_t)(bn + b_n)*ldb + k0 + b_k];
            Bs[b_k+0][b_n] = v.x; Bs[b_k+1][b_n] = v.y;
            Bs[b_k+2][b_n] = v.z; Bs[b_k+3][b_n] = v.w;
        }
        __syncthreads();

        #pragma unroll
        for (int k = 0; k < BK; k++) {
            float rm[TM], rn[TN];
            #pragma unroll
            for (int i = 0; i < TM; i++) rm[i] = As[k][ty*TM + i];
            #pragma unroll
            for (int j = 0; j < TN; j++) rn[j] = Bs[k][tx*TN + j];
            #pragma unroll
            for (int i = 0; i < TM; i++)
                #pragma unroll
                for (int j = 0; j < TN; j++)
                    acc[i][j] += rm[i] * rn[j];
        }
        __syncthreads();
    }

    #pragma unroll
    for (int i = 0; i < TM; i++) {
        const int m = bm + ty*TM + i;
        #pragma unroll
        for (int j = 0; j < TN; j++) {
            const int n = bn + tx*TN + j;
            C[(size_t)m*ldc + n] = acc[i][j];
        }
    }
}

// ---------------- depthwise causal conv(k=4) + bias + silu ----------------
__global__ __launch_bounds__(256)
void conv_silu_kernel(const float* __restrict__ xz,
                      const float* __restrict__ w,
                      const float* __restrict__ bias,
                      float* __restrict__ xc)
{
    const int d = blockIdx.x * blockDim.x + threadIdx.x;
    const int b = blockIdx.y;
    const float w0 = w[d*4+0], w1 = w[d*4+1], w2 = w[d*4+2], w3 = w[d*4+3];
    const float bi = bias[d];
    const float* px = xz + (size_t)b * L_ * EI + d;
    float*       po = xc + (size_t)b * L_ * DI + d;

    float x0 = 0.f, x1 = 0.f, x2 = 0.f;
    #pragma unroll 4
    for (int l = 0; l < L_; l++) {
        float x3 = px[(size_t)l * EI];
        float v  = w0*x0 + w1*x1 + w2*x2 + w3*x3 + bi;
        v = v / (1.0f + __expf(-v));
        po[(size_t)l * DI] = v;
        x0 = x1; x1 = x2; x2 = x3;
    }
}

// ---------------- selective scan (sequential over L) ----------------
__global__ __launch_bounds__(128)
void scan_kernel(const float* __restrict__ xz,
                 const float* __restrict__ xc,
                 const float* __restrict__ dt,
                 const float* __restrict__ xdbl,
                 const float* __restrict__ A_log,
                 const float* __restrict__ Dp,
                 float* __restrict__ y)
{
    const int b = blockIdx.y;
    const int d = blockIdx.x * blockDim.x + threadIdx.x;
    __shared__ float sBC[2][32];

    float negA[DS];
    #pragma unroll
    for (int n = 0; n < DS; n++) negA[n] = -__expf(A_log[d*DS + n]);

    bool chain = (negA[0] != 0.0f);
    #pragma unroll
    for (int n = 1; n < DS; n++) {
        float r = negA[n] - (float)(n+1) * negA[0];
        if (fabsf(r) > 1e-4f * fabsf(negA[n])) chain = false;
    }

    const float Dd = Dp[d];
    float h[DS];
    #pragma unroll
    for (int n = 0; n < DS; n++) h[n] = 0.0f;

    const size_t rb = (size_t)b * L_;
    const float* pdt = dt   + rb * DI + d;
    const float* pxc = xc   + rb * DI + d;
    const float* pz  = xz   + rb * EI + DI + d;
    const float* pbc = xdbl + rb * XD + DTR;
    float*       py  = y    + rb * DI + d;

    if (threadIdx.x < 32) sBC[0][threadIdx.x] = pbc[threadIdx.x];
    float dt_c = pdt[0], x_c = pxc[0], z_c = pz[0];
    __syncthreads();

    float dt_n = 0.f, x_n = 0.f, z_n = 0.f;
    for (int l = 0; l < L_; l++) {
        const int cur = l & 1, nxt = cur ^ 1;
        if (l + 1 < L_) {
            if (threadIdx.x < 32)
                sBC[nxt][threadIdx.x] = pbc[(size_t)(l+1) * XD + threadIdx.x];
            dt_n = pdt[(size_t)(l+1) * DI];
            x_n  = pxc[(size_t)(l+1) * DI];
            z_n  = pz [(size_t)(l+1) * EI];
        }

        const float dtv = dt_c;
        float dA[DS];
        if (chain) {
            float base = __expf(dtv * negA[0]);
            dA[0] = base;
            dA[1] = base * base;
            #pragma unroll
            for (int n = 2; n < DS; n++)
                dA[n] = dA[(n-1) >> 1] * dA[n >> 1];
        } else {
            #pragma unroll
            for (int n = 0; n < DS; n++) dA[n] = __expf(dtv * negA[n]);
        }

        const float du = dtv * x_c;
        float yv = 0.0f;
        #pragma unroll
        for (int n = 0; n < DS; n++) {
            h[n] = h[n] * dA[n] + du * sBC[cur][n];
            yv  += h[n] * sBC[cur][16 + n];
        }
        yv += x_c * Dd;
        const float zs = z_c / (1.0f + __expf(-z_c));
        py[(size_t)l * DI] = yv * zs;

        dt_c = dt_n; x_c = x_n; z_c = z_n;
        __syncthreads();
    }
}

// ---------------- launch ----------------
extern "C" void kernel_launch(void* const* d_in, const int* in_sizes, int n_in,
                              void* d_out, int out_size)
{
    const float* hs    = (const float*)d_in[0];
    const float* w_in  = (const float*)d_in[1];
    const float* convw = (const float*)d_in[2];
    const float* convb = (const float*)d_in[3];
    const float* xpw   = (const float*)d_in[4];
    const float* dtw   = (const float*)d_in[5];
    const float* dtb   = (const float*)d_in[6];
    const float* outw  = (const float*)d_in[7];
    const float* Alog  = (const float*)d_in[8];
    const float* Dp    = (const float*)d_in[9];
    float*       out   = (float*)d_out;

    float *xz, *xc, *xdbl, *dtb_, *yb;
    cudaGetSymbolAddress((void**)&xz,   g_xz);
    cudaGetSymbolAddress((void**)&xc,   g_xc);
    cudaGetSymbolAddress((void**)&xdbl, g_xdbl);
    cudaGetSymbolAddress((void**)&dtb_, g_dt);
    cudaGetSymbolAddress((void**)&yb,   g_y);

    const dim3 t256(256);

    // 1) in_proj: xz[ML,EI] = hs * w_in^T   (tf32 tensor cores)
    mma_gemm<0><<<dim3(EI/128, ML/128), t256>>>(
        ML, EI, DM, hs, DM, w_in, DM, xz, EI, nullptr);

    // 2) depthwise conv + silu
    conv_silu_kernel<<<dim3(DI/256, B_), t256>>>(xz, convw, convb, xc);

    // 3) x_proj (fp32, N=160 small)
    sgemm_kernel<64,32,16,4,2><<<dim3(XD/32, ML/64), t256>>>(
        ML, XD, DI, xc, DI, xpw, DI, xdbl, XD);

    // 4) dt_proj + softplus (tf32)
    mma_gemm<1><<<dim3(DI/128, ML/128), t256>>>(
        ML, DI, DTR, xdbl, XD, dtw, DTR, dtb_, DI, dtb);

    // 5) selective scan
    scan_kernel<<<dim3(DI/128, B_), dim3(128)>>>(
        xz, xc, dtb_, xdbl, Alog, Dp, yb);

    // 6) out_proj (tf32)
    mma_gemm<0><<<dim3(DM/128, ML/128), t256>>>(
        ML, DM, DI, yb, DI, outw, DI, out, DM, nullptr);
}

// round 4
// speedup vs baseline: 2.1927x; 1.1639x over previous
#include <cuda_runtime.h>
#include <cstdint>
#include <cstddef>

// ---------------- problem constants ----------------
#define B_   2
#define L_   2048
#define DM   2048          // d_model
#define DI   4096          // d_inner
#define EI   8192          // 2*d_inner
#define DS   16            // d_state
#define DTR  128           // dt_rank
#define XD   160           // dt_rank + 2*d_state
#define ML   (B_*L_)       // 4096 rows

// ---------------- scratch (device globals; no allocation allowed) ----------------
__device__ float g_xz  [(size_t)ML * EI];   // in_proj output [b*l, 8192]
__device__ float g_xc  [(size_t)ML * DI];   // conv+silu x    [b*l, 4096]
__device__ float g_xdbl[(size_t)ML * XD];   // x_proj output  [b*l, 160]
__device__ float g_dt  [(size_t)ML * DI];   // softplus(dt)   [b*l, 4096]
__device__ float g_y   [(size_t)ML * DI];   // scan output    [b*l, 4096]

// ================= TF32 tensor-core GEMM, cp.async 3-stage =================
// C[M,N] = A[M,K] * B[N,K]^T. BM=BN=128, BK=16, 256 thr, 8 warps 2(m)x4(n),
// warp tile 64x32. Raw fp32 in smem (XOR-swizzled), cvt->tf32 at fragment load.
// EPI: 0 = none, 1 = softplus(v + bias[n])

__device__ __forceinline__ unsigned f2tf32(float f) {
    unsigned u;
    asm("cvt.rna.tf32.f32 %0, %1;" : "=r"(u) : "f"(f));
    return u;
}

__device__ __forceinline__ void cp16(float* smem_dst, const float* gmem_src) {
    unsigned s = (unsigned)__cvta_generic_to_shared(smem_dst);
    asm volatile("cp.async.cg.shared.global [%0], [%1], 16;\n" :: "r"(s), "l"(gmem_src));
}
__device__ __forceinline__ void cp_commit() {
    asm volatile("cp.async.commit_group;\n");
}
__device__ __forceinline__ void cp_wait1() {
    asm volatile("cp.async.wait_group 1;\n");
}

#define TSZ 2048   // floats per stage per matrix (128 rows * 16)

template<int EPI>
__global__ __launch_bounds__(256)
void mma_gemm(int M, int N, int K,
              const float* __restrict__ A, int lda,
              const float* __restrict__ Bw, int ldb,
              float* __restrict__ C, int ldc,
              const float* __restrict__ bias)
{
    extern __shared__ float smem[];
    float* As = smem;            // 3 stages * 2048
    float* Bs = smem + 3*TSZ;    // 3 stages * 2048

    const int tid  = threadIdx.x;
    const int lane = tid & 31;
    const int warp = tid >> 5;
    const int wm   = (warp & 1) * 64;
    const int wn   = (warp >> 1) * 32;
    const int bm   = blockIdx.y * 128;
    const int bn   = blockIdx.x * 128;

    // ---- loader indices (cp.async, 16B per op, 4 ops/thread) ----
    const int lr  = tid >> 2;                      // row 0..63 (and +64)
    const int q   = tid & 3;                       // k-quad
    const int swl = (lr ^ (lr >> 2)) & 3;          // row swizzle
    const int dA0 = lr*16 + ((q ^ swl) << 2);      // same swizzle for row+64
    const int dA1 = dA0 + 64*16;

    const float* gA0 = A  + (size_t)(bm + lr)      * lda + q*4;
    const float* gA1 = A  + (size_t)(bm + lr + 64) * lda + q*4;
    const float* gB0 = Bw + (size_t)(bn + lr)      * ldb + q*4;
    const float* gB1 = Bw + (size_t)(bn + lr + 64) * ldb + q*4;

    // ---- fragment indices ----
    const int u    = lane >> 2;                    // 0..7
    const int li   = lane & 3;
    const int su   = (u ^ (u >> 2)) & 3;           // swizzle for rows = u mod 16
    const int a_row = wm + u;
    const int b_row = wn + u;

    float acc[4][4][4];
    #pragma unroll
    for (int i = 0; i < 4; i++)
        #pragma unroll
        for (int j = 0; j < 4; j++)
            #pragma unroll
            for (int r = 0; r < 4; r++) acc[i][j][r] = 0.0f;

    const int KT = K / 16;

    // ---- prologue: stage 0 and 1 ----
    {
        cp16(As + dA0, gA0); cp16(As + dA1, gA1);
        cp16(Bs + dA0, gB0); cp16(Bs + dA1, gB1);
        cp_commit();
        cp16(As + TSZ + dA0, gA0 + 16); cp16(As + TSZ + dA1, gA1 + 16);
        cp16(Bs + TSZ + dA0, gB0 + 16); cp16(Bs + TSZ + dA1, gB1 + 16);
        cp_commit();
    }
    cp_wait1();
    __syncthreads();

    for (int kt = 0; kt < KT; kt++) {
        const int cur = kt % 3;
        // issue stage kt+2
        if (kt + 2 < KT) {
            const int st = (kt + 2) % 3;
            const size_t ko = (size_t)(kt + 2) * 16;
            cp16(As + st*TSZ + dA0, gA0 + ko); cp16(As + st*TSZ + dA1, gA1 + ko);
            cp16(Bs + st*TSZ + dA0, gB0 + ko); cp16(Bs + st*TSZ + dA1, gB1 + ko);
        }
        cp_commit();

        // ---- compute on stage cur ----
        const float* asb = As + cur*TSZ;
        const float* bsb = Bs + cur*TSZ;
        #pragma unroll
        for (int ks = 0; ks < 2; ks++) {
            // column offsets: k = ks*8 + li (+4); rows r and r+8 differ by sw^2
            const int c0  = (((2*ks + 0) ^ su    ) << 2) + li;
            const int c1  = (((2*ks + 1) ^ su    ) << 2) + li;
            const int c0h = (((2*ks + 0) ^ su ^ 2) << 2) + li;
            const int c1h = (((2*ks + 1) ^ su ^ 2) << 2) + li;

            unsigned af[4][4];
            unsigned bf[4][2];
            #pragma unroll
            for (int i = 0; i < 4; i++) {
                const int r = (a_row + i*16) * 16;
                af[i][0] = f2tf32(asb[r         + c0 ]);
                af[i][1] = f2tf32(asb[r + 8*16  + c0h]);
                af[i][2] = f2tf32(asb[r         + c1 ]);
                af[i][3] = f2tf32(asb[r + 8*16  + c1h]);
            }
            #pragma unroll
            for (int j = 0; j < 4; j++) {
                const int r = (b_row + j*8) * 16;
                bf[j][0] = f2tf32(bsb[r + ((j & 1) ? c0h : c0)]);
                bf[j][1] = f2tf32(bsb[r + ((j & 1) ? c1h : c1)]);
            }
            #pragma unroll
            for (int i = 0; i < 4; i++)
                #pragma unroll
                for (int j = 0; j < 4; j++) {
                    asm volatile(
                        "mma.sync.aligned.m16n8k8.row.col.f32.tf32.tf32.f32 "
                        "{%0,%1,%2,%3}, {%4,%5,%6,%7}, {%8,%9}, {%0,%1,%2,%3};"
                        : "+f"(acc[i][j][0]), "+f"(acc[i][j][1]),
                          "+f"(acc[i][j][2]), "+f"(acc[i][j][3])
                        : "r"(af[i][0]), "r"(af[i][1]), "r"(af[i][2]), "r"(af[i][3]),
                          "r"(bf[j][0]), "r"(bf[j][1]));
                }
        }

        cp_wait1();
        __syncthreads();
    }

    // ---- epilogue ----
    #pragma unroll
    for (int i = 0; i < 4; i++) {
        const int r0 = bm + wm + i*16 + u;
        #pragma unroll
        for (int j = 0; j < 4; j++) {
            const int c0 = bn + wn + j*8 + li*2;
            float v0 = acc[i][j][0], v1 = acc[i][j][1];
            float v2 = acc[i][j][2], v3 = acc[i][j][3];
            if (EPI == 1) {
                const float bA = bias[c0], bB = bias[c0+1];
                v0 += bA; v1 += bB; v2 += bA; v3 += bB;
                v0 = (v0 > 20.0f) ? v0 : log1pf(__expf(v0));
                v1 = (v1 > 20.0f) ? v1 : log1pf(__expf(v1));
                v2 = (v2 > 20.0f) ? v2 : log1pf(__expf(v2));
                v3 = (v3 > 20.0f) ? v3 : log1pf(__expf(v3));
            }
            *(float2*)&C[(size_t)r0 * ldc + c0]     = make_float2(v0, v1);
            *(float2*)&C[(size_t)(r0+8) * ldc + c0] = make_float2(v2, v3);
        }
    }
}

// ---------------- fp32 tiled SGEMM (x_proj: N=160) ----------------
template<int BM, int BN, int BK, int TM, int TN>
__global__ __launch_bounds__(256)
void sgemm_kernel(int M, int N, int K,
                  const float* __restrict__ A, int lda,
                  const float* __restrict__ Bw, int ldb,
                  float* __restrict__ C, int ldc)
{
    __shared__ float As[BK][BM];
    __shared__ float Bs[BK][BN];

    const int tid = threadIdx.x;
    const int tx  = tid & 15;
    const int ty  = tid >> 4;
    const int bm  = blockIdx.y * BM;
    const int bn  = blockIdx.x * BN;

    float acc[TM][TN];
    #pragma unroll
    for (int i = 0; i < TM; i++)
        #pragma unroll
        for (int j = 0; j < TN; j++) acc[i][j] = 0.0f;

    const int a_m = tid / (BK/4);
    const int a_k = (tid % (BK/4)) * 4;
    const int b_n = tid / (BK/4);
    const int b_k = (tid % (BK/4)) * 4;

    for (int k0 = 0; k0 < K; k0 += BK) {
        if (tid < (BM*BK/4)) {
            float4 v = *(const float4*)&A[(size_t)(bm + a_m)*lda + k0 + a_k];
            As[a_k+0][a_m] = v.x; As[a_k+1][a_m] = v.y;
            As[a_k+2][a_m] = v.z; As[a_k+3][a_m] = v.w;
        }
        if (tid < (BN*BK/4)) {
            float4 v = *(const float4*)&Bw[(size_t)(bn + b_n)*ldb + k0 + b_k];
            Bs[b_k+0][b_n] = v.x; Bs[b_k+1][b_n] = v.y;
            Bs[b_k+2][b_n] = v.z; Bs[b_k+3][b_n] = v.w;
        }
        __syncthreads();

        #pragma unroll
        for (int k = 0; k < BK; k++) {
            float rm[TM], rn[TN];
            #pragma unroll
            for (int i = 0; i < TM; i++) rm[i] = As[k][ty*TM + i];
            #pragma unroll
            for (int j = 0; j < TN; j++) rn[j] = Bs[k][tx*TN + j];
            #pragma unroll
            for (int i = 0; i < TM; i++)
                #pragma unroll
                for (int j = 0; j < TN; j++)
                    acc[i][j] += rm[i] * rn[j];
        }
        __syncthreads();
    }

    #pragma unroll
    for (int i = 0; i < TM; i++) {
        const int m = bm + ty*TM + i;
        #pragma unroll
        for (int j = 0; j < TN; j++) {
            const int n = bn + tx*TN + j;
            C[(size_t)m*ldc + n] = acc[i][j];
        }
    }
}

// ---------------- depthwise causal conv(k=4) + bias + silu ----------------
__global__ __launch_bounds__(256)
void conv_silu_kernel(const float* __restrict__ xz,
                      const float* __restrict__ w,
                      const float* __restrict__ bias,
                      float* __restrict__ xc)
{
    const int d = blockIdx.x * blockDim.x + threadIdx.x;
    const int b = blockIdx.y;
    const float w0 = w[d*4+0], w1 = w[d*4+1], w2 = w[d*4+2], w3 = w[d*4+3];
    const float bi = bias[d];
    const float* px = xz + (size_t)b * L_ * EI + d;
    float*       po = xc + (size_t)b * L_ * DI + d;

    float x0 = 0.f, x1 = 0.f, x2 = 0.f;
    #pragma unroll 4
    for (int l = 0; l < L_; l++) {
        float x3 = px[(size_t)l * EI];
        float v  = w0*x0 + w1*x1 + w2*x2 + w3*x3 + bi;
        v = v / (1.0f + __expf(-v));
        po[(size_t)l * DI] = v;
        x0 = x1; x1 = x2; x2 = x3;
    }
}

// ---------------- selective scan (sequential over L) ----------------
__global__ __launch_bounds__(128)
void scan_kernel(const float* __restrict__ xz,
                 const float* __restrict__ xc,
                 const float* __restrict__ dt,
                 const float* __restrict__ xdbl,
                 const float* __restrict__ A_log,
                 const float* __restrict__ Dp,
                 float* __restrict__ y)
{
    const int b = blockIdx.y;
    const int d = blockIdx.x * blockDim.x + threadIdx.x;
    __shared__ float sBC[2][32];

    float negA[DS];
    #pragma unroll
    for (int n = 0; n < DS; n++) negA[n] = -__expf(A_log[d*DS + n]);

    bool chain = (negA[0] != 0.0f);
    #pragma unroll
    for (int n = 1; n < DS; n++) {
        float r = negA[n] - (float)(n+1) * negA[0];
        if (fabsf(r) > 1e-4f * fabsf(negA[n])) chain = false;
    }

    const float Dd = Dp[d];
    float h[DS];
    #pragma unroll
    for (int n = 0; n < DS; n++) h[n] = 0.0f;

    const size_t rb = (size_t)b * L_;
    const float* pdt = dt   + rb * DI + d;
    const float* pxc = xc   + rb * DI + d;
    const float* pz  = xz   + rb * EI + DI + d;
    const float* pbc = xdbl + rb * XD + DTR;
    float*       py  = y    + rb * DI + d;

    if (threadIdx.x < 32) sBC[0][threadIdx.x] = pbc[threadIdx.x];
    float dt_c = pdt[0], x_c = pxc[0], z_c = pz[0];
    __syncthreads();

    float dt_n = 0.f, x_n = 0.f, z_n = 0.f;
    for (int l = 0; l < L_; l++) {
        const int cur = l & 1, nxt = cur ^ 1;
        if (l + 1 < L_) {
            if (threadIdx.x < 32)
                sBC[nxt][threadIdx.x] = pbc[(size_t)(l+1) * XD + threadIdx.x];
            dt_n = pdt[(size_t)(l+1) * DI];
            x_n  = pxc[(size_t)(l+1) * DI];
            z_n  = pz [(size_t)(l+1) * EI];
        }

        const float dtv = dt_c;
        float dA[DS];
        if (chain) {
            float base = __expf(dtv * negA[0]);
            dA[0] = base;
            dA[1] = base * base;
            #pragma unroll
            for (int n = 2; n < DS; n++)
                dA[n] = dA[(n-1) >> 1] * dA[n >> 1];
        } else {
            #pragma unroll
            for (int n = 0; n < DS; n++) dA[n] = __expf(dtv * negA[n]);
        }

        const float du = dtv * x_c;
        float yv = 0.0f;
        #pragma unroll
        for (int n = 0; n < DS; n++) {
            h[n] = h[n] * dA[n] + du * sBC[cur][n];
            yv  += h[n] * sBC[cur][16 + n];
        }
        yv += x_c * Dd;
        const float zs = z_c / (1.0f + __expf(-z_c));
        py[(size_t)l * DI] = yv * zs;

        dt_c = dt_n; x_c = x_n; z_c = z_n;
        __syncthreads();
    }
}

// ---------------- launch ----------------
extern "C" void kernel_launch(void* const* d_in, const int* in_sizes, int n_in,
                              void* d_out, int out_size)
{
    const float* hs    = (const float*)d_in[0];
    const float* w_in  = (const float*)d_in[1];
    const float* convw = (const float*)d_in[2];
    const float* convb = (const float*)d_in[3];
    const float* xpw   = (const float*)d_in[4];
    const float* dtw   = (const float*)d_in[5];
    const float* dtb   = (const float*)d_in[6];
    const float* outw  = (const float*)d_in[7];
    const float* Alog  = (const float*)d_in[8];
    const float* Dp    = (const float*)d_in[9];
    float*       out   = (float*)d_out;

    float *xz, *xc, *xdbl, *dtb_, *yb;
    cudaGetSymbolAddress((void**)&xz,   g_xz);
    cudaGetSymbolAddress((void**)&xc,   g_xc);
    cudaGetSymbolAddress((void**)&xdbl, g_xdbl);
    cudaGetSymbolAddress((void**)&dtb_, g_dt);
    cudaGetSymbolAddress((void**)&yb,   g_y);

    const dim3 t256(256);
    const size_t gsmem = 6 * TSZ * sizeof(float);   // 49152 = default 48KB limit

    // 1) in_proj: xz[ML,EI] = hs * w_in^T   (tf32 tensor cores)
    mma_gemm<0><<<dim3(EI/128, ML/128), t256, gsmem>>>(
        ML, EI, DM, hs, DM, w_in, DM, xz, EI, nullptr);

    // 2) depthwise conv + silu
    conv_silu_kernel<<<dim3(DI/256, B_), t256>>>(xz, convw, convb, xc);

    // 3) x_proj (fp32, N=160 small)
    sgemm_kernel<64,32,16,4,2><<<dim3(XD/32, ML/64), t256>>>(
        ML, XD, DI, xc, DI, xpw, DI, xdbl, XD);

    // 4) dt_proj + softplus (tf32)
    mma_gemm<1><<<dim3(DI/128, ML/128), t256, gsmem>>>(
        ML, DI, DTR, xdbl, XD, dtw, DTR, dtb_, DI, dtb);

    // 5) selective scan
    scan_kernel<<<dim3(DI/128, B_), dim3(128)>>>(
        xz, xc, dtb_, xdbl, Alog, Dp, yb);

    // 6) out_proj (tf32)
    mma_gemm<0><<<dim3(DM/128, ML/128), t256, gsmem>>>(
        ML, DM, DI, yb, DI, outw, DI, out, DM, nullptr);
}